// round 6
// baseline (speedup 1.0000x reference)
#include <cuda_runtime.h>
#include <math.h>

// Brunel network forward, GB300 — round 6.
// CSA bit-sliced counting + width-halving cross-lane butterfly,
// uint4 idx loads, 2 blocks/SM occupancy. Numerics = round 4 (table-exact).

#define NN 10000
#define CC 1000
#define CE 800
#define BB 8
#define TT 200
#define WS 8
#define NWIN 25
#define REFS 20
#define TAB_I 201
#define NWARP 16
#define THREADS 512
#define GRID 296
#define CHUNK 34
#define SMEM_BYTES (NN * 8)   // 80000

typedef unsigned long long u64;
typedef unsigned int u32;

__device__ u32  g_excw[NN * 400];   // word W of neuron n = idx[n][2W] | idx[n][2W+1]<<16
__device__ u32  g_inhw[NN * 100];
__device__ float g_v[BB * NN];
__device__ int   g_ref[BB * NN];
__device__ u64   g_spk[3][NN];
__device__ float g_tab2[801 * TAB_I];

__global__ void prep_kernel(const int* __restrict__ idx) {
    int i = blockIdx.x * blockDim.x + threadIdx.x;
    if (i >= NN * 500) return;
    int n = i / 500, w = i % 500;
    if (w < 400) {
        int c = 2 * w;
        u32 lo = (u32)idx[n * CC + c], hi = (u32)idx[n * CC + c + 1];
        g_excw[n * 400 + w] = lo | (hi << 16);
    } else {
        int c = CE + 2 * (w - 400);
        u32 lo = (u32)idx[n * CC + c], hi = (u32)idx[n * CC + c + 1];
        g_inhw[n * 100 + (w - 400)] = lo | (hi << 16);
    }
}

__global__ void init_kernel(const float* __restrict__ w) {
    int i = blockIdx.x * blockDim.x + threadIdx.x;
    int stride = gridDim.x * blockDim.x;
    for (int k = i; k < BB * NN; k += stride) { g_v[k] = 0.0f; g_ref[k] = 0; }
    u64* sp = &g_spk[0][0];
    for (int k = i; k < 3 * NN; k += stride) sp[k] = 0ull;
    if (i < 801) {
        float we = w[0];
        float wi = w[CE];
        float a = 0.0f;
        for (int k = 0; k < i; k++) a = __fadd_rn(a, we);
        g_tab2[i * TAB_I] = a;
        for (int j = 1; j < TAB_I; j++) {
            a = __fadd_rn(a, wi);
            g_tab2[i * TAB_I + j] = a;
        }
    }
}

__device__ __forceinline__ u64 csa(u64& acc, u64 a, u64 b) {
    u64 u = acc ^ a;
    u64 carry = (acc & a) | (u & b);
    acc = u ^ b;
    return carry;
}

// Width-halving butterfly reduction.
// In: P0 u64 planes (vertical counters over 64 positions = 8 steps x 8 batches).
// Out: packed u32 = cnt(pos p0=0) | cnt(pos p0=1)<<16, where this lane owns
// positions with bits p5..p1 = lane bits 0..4.
template<int P0>
__device__ __forceinline__ u32 hreduce(const u64* q, int lane) {
    const u32 full = 0xFFFFFFFFu;
    u32 p[P0 + 5];
    // Level 0: u64 -> u32 halves, partner = lane^1
    {
        bool hi_keep = (lane & 1);
        u32 c = 0;
        #pragma unroll
        for (int k = 0; k < P0; k++) {
            u32 lo = (u32)q[k], hi = (u32)(q[k] >> 32);
            u32 give = hi_keep ? lo : hi;
            u32 own  = hi_keep ? hi : lo;
            u32 r = __shfl_xor_sync(full, give, 1);
            u32 x = own ^ r;
            if (k == 0) { p[0] = x; c = own & r; }
            else        { p[k] = x ^ c; c = (own & r) | (x & c); }
        }
        p[P0] = c;
    }
    // Levels 1..4: widths 16,8,4,2 (no masking; garbage stays in high bits)
    #pragma unroll
    for (int lev = 1; lev <= 4; lev++) {
        const int W = 32 >> lev;
        const int delta = 1 << lev;
        const int P = P0 + lev;
        u32 sh = ((lane >> lev) & 1) ? (u32)W : 0u;
        u32 c = 0;
        #pragma unroll
        for (int k = 0; k < P0 + 5; k++) {
            if (k < P) {
                u32 r = __shfl_xor_sync(full, p[k], delta);
                u32 own = p[k] >> sh;
                u32 rec = r >> sh;
                u32 x = own ^ rec;
                if (k == 0) { p[0] = x; c = own & rec; }
                else        { p[k] = x ^ c; c = (own & rec) | (x & c); }
            }
        }
        p[P] = c;
    }
    u32 c0 = 0, c1 = 0;
    #pragma unroll
    for (int k = 0; k < P0 + 5; k++) {
        c0 |= (p[k] & 1u) << k;
        c1 |= ((p[k] >> 1) & 1u) << k;
    }
    return c0 | (c1 << 16);
}

__global__ void __launch_bounds__(THREADS, 2) win_kernel(
    const float* __restrict__ ext,
    float* __restrict__ out_spk,
    float* __restrict__ out_v,
    int t0, int kwin, float decay)
{
    extern __shared__ u64 s_mask[];   // [NN]: byte s = delayed step, bit b = batch

    const int tid  = threadIdx.x;
    const int lane = tid & 31;
    const int warp = tid >> 5;
    const u32 full = 0xFFFFFFFFu;

    if (kwin > 0) {
        const u64* A = g_spk[(kwin + 1) % 3];   // window k-2
        const u64* B = g_spk[(kwin + 2) % 3];   // window k-1
        for (int i = tid; i < NN; i += THREADS)
            s_mask[i] = (A[i] >> 8) | (B[i] << 56);
        __syncthreads();
    }

    const int nbeg = blockIdx.x * CHUNK;
    const int nend = (nbeg + CHUNK < NN) ? nbeg + CHUNK : NN;

    for (int n = nbeg + warp; n < nend; n += NWARP) {
        int ce_[WS], ci_[WS];

        if (kwin > 0) {
            u32 packE, packI;
            {
                // ---- exc gather: 3 uint4 rounds (24 masks) + u32 tail (2 masks, lanes<16)
                u64 v1 = 0, v2 = 0, v4 = 0, v8 = 0, v16 = 0;
                const u32* ew = g_excw + n * 400;
                const uint4* ew4 = (const uint4*)ew;
                #pragma unroll
                for (int r = 0; r < 3; r++) {
                    uint4 q = ew4[r * 32 + lane];
                    u64 m0 = s_mask[q.x & 0xFFFFu], m1 = s_mask[q.x >> 16];
                    u64 m2 = s_mask[q.y & 0xFFFFu], m3 = s_mask[q.y >> 16];
                    u64 m4 = s_mask[q.z & 0xFFFFu], m5 = s_mask[q.z >> 16];
                    u64 m6 = s_mask[q.w & 0xFFFFu], m7 = s_mask[q.w >> 16];
                    u64 c1 = csa(v1, m0, m1);
                    u64 c2 = csa(v1, m2, m3);
                    u64 dA = csa(v2, c1, c2);
                    u64 c3 = csa(v1, m4, m5);
                    u64 c4 = csa(v1, m6, m7);
                    u64 dB = csa(v2, c3, c4);
                    u64 cc = csa(v4, dA, dB);
                    u64 t  = v8 & cc; v8 ^= cc; v16 ^= t;
                }
                {
                    u64 m0 = 0, m1 = 0;
                    if (lane < 16) {
                        u32 w = ew[384 + lane];
                        m0 = s_mask[w & 0xFFFFu]; m1 = s_mask[w >> 16];
                    }
                    u64 c1 = csa(v1, m0, m1);
                    u64 t1 = v2 & c1; v2 ^= c1;
                    u64 t2 = v4 & t1; v4 ^= t1;
                    u64 t3 = v8 & t2; v8 ^= t2;
                    v16 ^= t3;
                }
                u64 e[5] = { v1, v2, v4, v8, v16 };
                packE = hreduce<5>(e, lane);
            }
            {
                // ---- inh gather: 1 uint4 (8 masks, lanes<25)
                u64 u1 = 0, u2 = 0, u4 = 0, u8 = 0;
                u64 m0 = 0, m1 = 0, m2 = 0, m3 = 0, m4 = 0, m5 = 0, m6 = 0, m7 = 0;
                if (lane < 25) {
                    uint4 q = ((const uint4*)(g_inhw + n * 100))[lane];
                    m0 = s_mask[q.x & 0xFFFFu]; m1 = s_mask[q.x >> 16];
                    m2 = s_mask[q.y & 0xFFFFu]; m3 = s_mask[q.y >> 16];
                    m4 = s_mask[q.z & 0xFFFFu]; m5 = s_mask[q.z >> 16];
                    m6 = s_mask[q.w & 0xFFFFu]; m7 = s_mask[q.w >> 16];
                }
                u64 c1 = csa(u1, m0, m1);
                u64 c2 = csa(u1, m2, m3);
                u64 dA = csa(u2, c1, c2);
                u64 c3 = csa(u1, m4, m5);
                u64 c4 = csa(u1, m6, m7);
                u64 dB = csa(u2, c3, c4);
                u64 cc = csa(u4, dA, dB);
                u8 ^= cc;
                u64 f[4] = { u1, u2, u4, u8 };
                packI = hreduce<4>(f, lane);
            }

            // ---- redistribute: position 8s+b owned by lane
            //      s2 | s1<<1 | s0<<2 | b2<<3 | b1<<4, slot = b0
            const int hb = (((lane >> 2) & 1) << 3) | (((lane >> 1) & 1) << 4);
            const int sh = (lane & 1) * 16;
            #pragma unroll
            for (int s = 0; s < WS; s++) {
                int src = ((s >> 2) & 1) | (s & 2) | ((s & 1) << 2) | hb;
                u32 pe = __shfl_sync(full, packE, src);
                u32 pi = __shfl_sync(full, packI, src);
                ce_[s] = (pe >> sh) & 0xFFFF;
                ci_[s] = (pi >> sh) & 0xFFFF;
            }
        } else {
            #pragma unroll
            for (int s = 0; s < WS; s++) { ce_[s] = 0; ci_[s] = 0; }
        }

        // ---- LIF epilogue: lanes 0..7 = batches (identical numerics to round 4)
        const bool act = (lane < 8);
        float v = 0.0f; int rf = 0;
        float acc[WS], ex[WS];
        if (act) {
            const int sid = lane * NN + n;
            v  = g_v[sid];
            rf = g_ref[sid];
            #pragma unroll
            for (int s = 0; s < WS; s++)
                acc[s] = g_tab2[ce_[s] * TAB_I + ci_[s]];
            #pragma unroll
            for (int s = 0; s < WS; s++)
                ex[s] = ext[((size_t)(t0 + s) * BB + lane) * NN + n];
        }
        u64 spk64 = 0ull;
        #pragma unroll
        for (int s = 0; s < WS; s++) {
            bool sp = false;
            if (act) {
                float vn = __fadd_rn(__fadd_rn(__fmul_rn(v, decay), acc[s]), ex[s]);
                if (rf > 0) vn = 10.0f;
                sp = (vn >= 20.0f);
                float vo = sp ? 10.0f : vn;
                int rm = rf - 1; if (rm < 0) rm = 0;
                rf = sp ? REFS : rm;
                v = vo;
                size_t o = ((size_t)(t0 + s) * BB + lane) * NN + n;
                out_spk[o] = sp ? 1.0f : 0.0f;
                out_v[o]   = vo;
            }
            u32 ball = __ballot_sync(full, sp);
            spk64 |= (u64)(ball & 0xFFu) << (8 * s);
        }
        if (act) {
            const int sid = lane * NN + n;
            g_v[sid] = v; g_ref[sid] = rf;
        }
        if (lane == 0) g_spk[kwin % 3][n] = spk64;
    }
}

extern "C" void kernel_launch(void* const* d_in, const int* in_sizes, int n_in,
                              void* d_out, int out_size)
{
    const float* ext = (const float*)d_in[0];
    const float* w   = (const float*)d_in[1];
    const int*   idx = (const int*)d_in[2];

    float* out     = (float*)d_out;
    float* out_spk = out;
    float* out_v   = out + (size_t)TT * BB * NN;

    float decay = (float)exp(-0.005);

    cudaFuncSetAttribute(win_kernel, cudaFuncAttributeMaxDynamicSharedMemorySize,
                         SMEM_BYTES);

    prep_kernel<<<(NN * 500 + 255) / 256, 256>>>(idx);
    init_kernel<<<160, 256>>>(w);

    for (int k = 0; k < NWIN; k++) {
        win_kernel<<<GRID, THREADS, SMEM_BYTES>>>(ext, out_spk, out_v,
                                                  k * WS, k, decay);
    }
}

// round 8
// speedup vs baseline: 1.6206x; 1.6206x over previous
#include <cuda_runtime.h>
#include <math.h>

// Brunel network forward, GB300 — round 8.
// Round 7 structure (4 neurons/warp, 3-level amortized butterfly, reversed
// batch-major masks) with the writeback bug fixed: per-lane direct byte
// stores replace the carry-corrupting multiply-spread + ballot.

#define NN 10000
#define CC 1000
#define CE 800
#define BB 8
#define TT 200
#define WS 8
#define NWIN 25
#define REFS 20
#define TAB_I 201
#define THREADS 288          // 9 warps x 4 neurons = 36 >= CHUNK
#define CHUNK 34
#define GRID 295             // 295*34 = 10030 >= NN
#define SENT 10000           // sentinel idx -> zero mask
#define SMEM_BYTES ((NN + 8) * 8)

typedef unsigned long long u64;
typedef unsigned int u32;

__device__ uint4 g_excp[NN * 13 * 8];   // [n][round 0..12][gl] : 8 packed u16 idx
__device__ uint4 g_inhp[NN * 4 * 8];    // [n][round 0..3][gl]
__device__ float g_v[BB * NN];
__device__ int   g_ref[BB * NN];
__device__ u64   g_spk[3][NN];          // byte q bit s = spike(batch rev3(q), step s)
__device__ float g_tab2[801 * TAB_I];

__global__ void prep_kernel(const int* __restrict__ idx) {
    int i = blockIdx.x * blockDim.x + threadIdx.x;
    const int NE = NN * 416;
    if (i < NE) {
        int w  = i & 3;
        int gl = (i >> 2) & 7;
        int r  = (i >> 5) % 13;
        int n  = i / 416;
        int cl = r * 8 + 2 * w;
        u32 lo = (cl     < 100) ? (u32)idx[n * CC + gl * 100 + cl]     : (u32)SENT;
        u32 hi = (cl + 1 < 100) ? (u32)idx[n * CC + gl * 100 + cl + 1] : (u32)SENT;
        ((u32*)g_excp)[i] = lo | (hi << 16);
    } else {
        int j = i - NE;
        if (j < NN * 128) {
            int w  = j & 3;
            int gl = (j >> 2) & 7;
            int r  = (j >> 5) & 3;
            int n  = j >> 7;
            int cl = r * 8 + 2 * w;
            u32 lo = (cl     < 25) ? (u32)idx[n * CC + CE + gl * 25 + cl]     : (u32)SENT;
            u32 hi = (cl + 1 < 25) ? (u32)idx[n * CC + CE + gl * 25 + cl + 1] : (u32)SENT;
            ((u32*)g_inhp)[j] = lo | (hi << 16);
        }
    }
}

__global__ void init_kernel(const float* __restrict__ w) {
    int i = blockIdx.x * blockDim.x + threadIdx.x;
    int stride = gridDim.x * blockDim.x;
    for (int k = i; k < BB * NN; k += stride) { g_v[k] = 0.0f; g_ref[k] = 0; }
    u64* sp = &g_spk[0][0];
    for (int k = i; k < 3 * NN; k += stride) sp[k] = 0ull;
    if (i < 801) {   // exact sequential sums: i adds of w[0], then j adds of w[CE]
        float we = w[0];
        float wi = w[CE];
        float a = 0.0f;
        for (int k = 0; k < i; k++) a = __fadd_rn(a, we);
        g_tab2[i * TAB_I] = a;
        for (int j = 1; j < TAB_I; j++) {
            a = __fadd_rn(a, wi);
            g_tab2[i * TAB_I + j] = a;
        }
    }
}

__device__ __forceinline__ u64 csa64(u64& acc, u64 a, u64 b) {
    u64 u = acc ^ a;
    u64 carry = (acc & a) | (u & b);
    acc = u ^ b;
    return carry;
}

// 3-level width-halving butterfly within each 8-lane group.
// In: P0 u64 vertical-counter planes over 64 positions (byte q, bit s).
// Out: P0+3 u32 planes; lane gl's low 8 bits = counts for byte q=rev3(gl)
// (= batch gl), field bit j = step j.
template<int P0>
__device__ __forceinline__ void bfly3(const u64* q, u32* p, int lane) {
    const u32 full = 0xFFFFFFFFu;
    {   // level 0: u64 -> u32 (position bit5 = q bit2), partner lane^1
        bool hk = (lane & 1);
        u32 c = 0;
        #pragma unroll
        for (int k = 0; k < P0; k++) {
            u32 lo = (u32)q[k], hi = (u32)(q[k] >> 32);
            u32 give = hk ? lo : hi;
            u32 own  = hk ? hi : lo;
            u32 r = __shfl_xor_sync(full, give, 1);
            u32 x = own ^ r;
            if (k == 0) { p[0] = x; c = own & r; }
            else        { p[k] = x ^ c; c = (own & r) | (x & c); }
        }
        p[P0] = c;
    }
    #pragma unroll
    for (int lev = 1; lev <= 2; lev++) {   // widths 16, 8
        const int W = (lev == 1) ? 16 : 8;
        const int P = P0 + lev;
        u32 sh = ((lane >> lev) & 1) ? (u32)W : 0u;
        u32 c = 0;
        #pragma unroll
        for (int k = 0; k < P0 + 3; k++) {
            if (k < P) {
                u32 r = __shfl_xor_sync(full, p[k], 1 << lev);
                u32 own = p[k] >> sh;
                u32 rec = r >> sh;
                u32 x = own ^ rec;
                if (k == 0) { p[0] = x; c = own & rec; }
                else        { p[k] = x ^ c; c = (own & rec) | (x & c); }
            }
        }
        p[P] = c;
    }
}

__global__ void __launch_bounds__(THREADS, 2) win_kernel(
    const float* __restrict__ ext,
    float* __restrict__ out_spk,
    float* __restrict__ out_v,
    int t0, int kwin, float decay)
{
    extern __shared__ u64 s_mask[];   // NN+1 entries (SENT -> 0)

    const int tid  = threadIdx.x;
    const int lane = tid & 31;
    const int warp = tid >> 5;

    if (kwin > 0) {
        // per-byte step shift: bit s = A bit s+1 (s<=6), bit 7 = B bit 0
        const u64* A = g_spk[(kwin + 1) % 3];   // window k-2
        const u64* B = g_spk[(kwin + 2) % 3];   // window k-1
        for (int i = tid; i < NN; i += THREADS) {
            u64 a = A[i], b = B[i];
            s_mask[i] = ((a >> 1) & 0x7F7F7F7F7F7F7F7Full)
                      | ((b & 0x0101010101010101ull) << 7);
        }
        if (tid == 0) s_mask[SENT] = 0ull;
        __syncthreads();
    }

    const int g   = lane >> 3;          // neuron within warp (0..3)
    const int gl  = lane & 7;           // group lane = batch
    const int ln  = warp * 4 + g;       // local neuron in block
    const int n   = blockIdx.x * CHUNK + ln;
    const bool act = (ln < CHUNK) && (n < NN);
    const int nc  = act ? n : 0;        // clamped for safe loads

    int ce_[WS], ci_[WS];

    if (kwin > 0) {
        // ---- per-lane CSA: exc 13 rounds (104 masks, 100 real) ----
        u64 e1=0,e2=0,e4=0,e8=0,e16=0,e32=0,e64=0;
        {
            const uint4* ep = g_excp + (size_t)nc * 104 + gl;
            #pragma unroll
            for (int r = 0; r < 13; r++) {
                uint4 q = ep[r * 8];
                u64 m0 = s_mask[q.x & 0xFFFFu], m1 = s_mask[q.x >> 16];
                u64 m2 = s_mask[q.y & 0xFFFFu], m3 = s_mask[q.y >> 16];
                u64 m4 = s_mask[q.z & 0xFFFFu], m5 = s_mask[q.z >> 16];
                u64 m6 = s_mask[q.w & 0xFFFFu], m7 = s_mask[q.w >> 16];
                u64 c1 = csa64(e1, m0, m1);
                u64 c2 = csa64(e1, m2, m3);
                u64 dA = csa64(e2, c1, c2);
                u64 c3 = csa64(e1, m4, m5);
                u64 c4 = csa64(e1, m6, m7);
                u64 dB = csa64(e2, c3, c4);
                u64 cc = csa64(e4, dA, dB);
                u64 t  = e8  & cc; e8  ^= cc;
                u64 t2 = e16 & t;  e16 ^= t;
                u64 t3 = e32 & t2; e32 ^= t2;
                e64 ^= t3;
            }
        }
        // ---- inh: 4 rounds (32 masks, 25 real) ----
        u64 f1=0,f2=0,f4=0,f8=0,f16=0;
        {
            const uint4* ip = g_inhp + (size_t)nc * 32 + gl;
            #pragma unroll
            for (int r = 0; r < 4; r++) {
                uint4 q = ip[r * 8];
                u64 m0 = s_mask[q.x & 0xFFFFu], m1 = s_mask[q.x >> 16];
                u64 m2 = s_mask[q.y & 0xFFFFu], m3 = s_mask[q.y >> 16];
                u64 m4 = s_mask[q.z & 0xFFFFu], m5 = s_mask[q.z >> 16];
                u64 m6 = s_mask[q.w & 0xFFFFu], m7 = s_mask[q.w >> 16];
                u64 c1 = csa64(f1, m0, m1);
                u64 c2 = csa64(f1, m2, m3);
                u64 dA = csa64(f2, c1, c2);
                u64 c3 = csa64(f1, m4, m5);
                u64 c4 = csa64(f1, m6, m7);
                u64 dB = csa64(f2, c3, c4);
                u64 cc = csa64(f4, dA, dB);
                u64 t  = f8 & cc; f8 ^= cc;
                f16 ^= t;
            }
        }

        u64 e[7] = { e1, e2, e4, e8, e16, e32, e64 };
        u64 f[5] = { f1, f2, f4, f8, f16 };
        u32 pe[10], pf[8];
        bfly3<7>(e, pe, lane);   // counts <= 832 < 1024
        bfly3<5>(f, pf, lane);   // counts <= 256

        // ---- extraction: lane gl owns batch gl, field bit j = step j ----
        #pragma unroll
        for (int s = 0; s < WS; s++) {
            u32 a = 0, b2 = 0;
            #pragma unroll
            for (int k = 0; k < 10; k++) a |= ((pe[k] >> s) & 1u) << k;
            #pragma unroll
            for (int k = 0; k < 8; k++)  b2 |= ((pf[k] >> s) & 1u) << k;
            ce_[s] = (int)a; ci_[s] = (int)b2;
        }
    } else {
        #pragma unroll
        for (int s = 0; s < WS; s++) { ce_[s] = 0; ci_[s] = 0; }
    }

    // ---- LIF epilogue: all 32 lanes active (4 neurons x 8 batches) ----
    const int b = gl;
    float v = 0.0f; int rf = 0;
    float acc[WS], ex[WS];
    if (act) {
        const int sid = b * NN + n;
        v  = g_v[sid];
        rf = g_ref[sid];
        #pragma unroll
        for (int s = 0; s < WS; s++)
            acc[s] = g_tab2[ce_[s] * TAB_I + ci_[s]];
        #pragma unroll
        for (int s = 0; s < WS; s++)
            ex[s] = ext[((size_t)(t0 + s) * BB + b) * NN + n];
    }

    u32 mybits = 0;   // this lane's (batch b) spike bits across the 8 steps
    #pragma unroll
    for (int s = 0; s < WS; s++) {
        if (act) {
            float vn = __fadd_rn(__fadd_rn(__fmul_rn(v, decay), acc[s]), ex[s]);
            if (rf > 0) vn = 10.0f;
            bool sp = (vn >= 20.0f);
            float vo = sp ? 10.0f : vn;
            int rm = rf - 1; if (rm < 0) rm = 0;
            rf = sp ? REFS : rm;
            v = vo;
            mybits |= (sp ? 1u : 0u) << s;
            size_t o = ((size_t)(t0 + s) * BB + b) * NN + n;
            out_spk[o] = sp ? 1.0f : 0.0f;
            out_v[o]   = vo;
        }
    }
    if (act) {
        const int sid = b * NN + n;
        g_v[sid] = v; g_ref[sid] = rf;
        // byte q holds batch rev3(q); this lane is batch gl -> byte rev3(gl)
        const int q = ((gl & 1) << 2) | (gl & 2) | ((gl >> 2) & 1);
        ((unsigned char*)&g_spk[kwin % 3][n])[q] = (unsigned char)mybits;
    }
}

extern "C" void kernel_launch(void* const* d_in, const int* in_sizes, int n_in,
                              void* d_out, int out_size)
{
    const float* ext = (const float*)d_in[0];
    const float* w   = (const float*)d_in[1];
    const int*   idx = (const int*)d_in[2];

    float* out     = (float*)d_out;
    float* out_spk = out;
    float* out_v   = out + (size_t)TT * BB * NN;

    float decay = (float)exp(-0.005);

    cudaFuncSetAttribute(win_kernel, cudaFuncAttributeMaxDynamicSharedMemorySize,
                         SMEM_BYTES);

    prep_kernel<<<(NN * 416 + NN * 128 + 255) / 256, 256>>>(idx);
    init_kernel<<<160, 256>>>(w);

    for (int k = 0; k < NWIN; k++) {
        win_kernel<<<GRID, THREADS, SMEM_BYTES>>>(ext, out_spk, out_v,
                                                  k * WS, k, decay);
    }
}